// round 10
// baseline (speedup 1.0000x reference)
#include <cuda_runtime.h>

// Bilinear 2x upsample, NHWC f32, 2x2-output-per-thread (R2/R6 body),
// GRID-STRIDE PERSISTENT: one wave of 592 CTAs loops over all tiles,
// eliminating ~30 wave transitions worth of DRAM ramp bubbles.
// in : (8, 256, 256, 64), out: (8, 512, 512, 64)

static constexpr int IN_H  = 256;
static constexpr int IN_W  = 256;
static constexpr int OUT_H = 512;
static constexpr int OUT_W = 512;
static constexpr int CV    = 16;       // float4 vectors per pixel (C=64)
static constexpr int GX    = 17;       // column-group tiles (17*16 = 272 >= 257)
static constexpr int GY    = 257;      // row groups
static constexpr int GB    = 8;        // batches
static constexpr int NTILE = GX * GY * GB;   // 34952
static constexpr int NB    = 592;      // 4 CTAs/SM * 148 SMs — single wave

__device__ __forceinline__ float4 lerp4(float4 a, float4 b, float wb) {
    float wa = 1.0f - wb;
    float4 r;
    r.x = a.x * wa + b.x * wb;
    r.y = a.y * wa + b.y * wb;
    r.z = a.z * wa + b.z * wb;
    r.w = a.w * wa + b.w * wb;
    return r;
}

__global__ __launch_bounds__(256)
void bilerp2x_gs_kernel(const float4* __restrict__ in, float4* __restrict__ out) {
    int cvec = threadIdx.x;                      // 0..15
    int ty   = threadIdx.y;                      // 0..15

    for (int tile = blockIdx.x; tile < NTILE; tile += NB) {
        int b   = tile / (GX * GY);
        int rem = tile - b * (GX * GY);
        int j   = rem / GX;                      // row group, 0..256
        int gx  = rem - j * GX;
        int i   = gx * 16 + ty;                  // column group, 0..271
        if (i > 256) continue;

        int ii = i - 1;
        int jj = j - 1;
        int x_lo = max(ii, 0);
        int x_hi = min(ii + 1, IN_W - 1);
        int y_lo = max(jj, 0);
        int y_hi = min(jj + 1, IN_H - 1);

        long in_b = (long)b * IN_H * IN_W * CV;
        const float4* r0 = in + in_b + (long)(y_lo * IN_W) * CV + cvec;
        const float4* r1 = in + in_b + (long)(y_hi * IN_W) * CV + cvec;

        float4 p00 = __ldg(r0 + (long)x_lo * CV);
        float4 p01 = __ldg(r0 + (long)x_hi * CV);
        float4 p10 = __ldg(r1 + (long)x_lo * CV);
        float4 p11 = __ldg(r1 + (long)x_hi * CV);

        float4 ta = lerp4(p00, p01, 0.25f);
        float4 tb = lerp4(p00, p01, 0.75f);
        float4 ba = lerp4(p10, p11, 0.25f);
        float4 bb = lerp4(p10, p11, 0.75f);

        int ox_a = 2 * i - 1;
        int ox_b = 2 * i;
        int oy_a = 2 * j - 1;
        int oy_b = 2 * j;

        bool wxa = (i >= 1);
        bool wxb = (i <= 255);
        bool wya = (j >= 1);
        bool wyb = (j <= 255);

        long out_b = (long)b * OUT_H * OUT_W * CV + cvec;

        if (wya) {  // oy_a, dy = 0.25
            long row = out_b + (long)(oy_a * OUT_W) * CV;
            if (wxa) out[row + (long)ox_a * CV] = lerp4(ta, ba, 0.25f);
            if (wxb) out[row + (long)ox_b * CV] = lerp4(tb, bb, 0.25f);
        }
        if (wyb) {  // oy_b, dy = 0.75
            long row = out_b + (long)(oy_b * OUT_W) * CV;
            if (wxa) out[row + (long)ox_a * CV] = lerp4(ta, ba, 0.75f);
            if (wxb) out[row + (long)ox_b * CV] = lerp4(tb, bb, 0.75f);
        }
    }
}

extern "C" void kernel_launch(void* const* d_in, const int* in_sizes, int n_in,
                              void* d_out, int out_size) {
    const float4* in  = (const float4*)d_in[0];
    float4*       out = (float4*)d_out;

    dim3 block(16, 16);
    dim3 grid(NB);
    bilerp2x_gs_kernel<<<grid, block>>>(in, out);
}

// round 11
// speedup vs baseline: 1.1265x; 1.1265x over previous
#include <cuda_runtime.h>

// FINAL: Bilinear 2x upsample, NHWC f32, 2x2-output-per-thread.
// in : (8, 256, 256, 64), out: (8, 512, 512, 64)
//
// Each thread loads the 2x2 input neighborhood (i-1..i, j-1..j) as float4
// channel chunks and writes the 2x2 output block (2i-1,2i) x (2j-1,2j) with
// fixed separable weights 0.25/0.75 (exact for the 2x half-pixel mapping).
// Edge clamping matches the reference _coords (clamp-at-0 + clamp-at-max).
//
// Measured at the chip's mixed read+write memory wall: ~6.35 TB/s sustained,
// traffic at the ~611 MB/replay floor (537 MB mandatory writes + residual
// reads), DRAM 80% of 8 TB/s spec. Ten structural/policy variants (wavefront
// reduction, 256-bit LDG/STG, L2 evict hints, persistent launch, occupancy
// 33-81%) all land within noise of this kernel; none moved the wall.

static constexpr int IN_H  = 256;
static constexpr int IN_W  = 256;
static constexpr int OUT_H = 512;
static constexpr int OUT_W = 512;
static constexpr int CV    = 16;   // float4 vectors per pixel (C=64)

__device__ __forceinline__ float4 lerp4(float4 a, float4 b, float wb) {
    float wa = 1.0f - wb;
    float4 r;
    r.x = a.x * wa + b.x * wb;
    r.y = a.y * wa + b.y * wb;
    r.z = a.z * wa + b.z * wb;
    r.w = a.w * wa + b.w * wb;
    return r;
}

__global__ __launch_bounds__(256)
void bilerp2x_final_kernel(const float4* __restrict__ in, float4* __restrict__ out) {
    int cvec = threadIdx.x;                      // 0..15 : channel chunk
    int i    = blockIdx.x * 16 + threadIdx.y;    // column group, 0..256
    int j    = blockIdx.y;                       // row group, 0..256
    int b    = blockIdx.z;
    if (i > 256) return;

    int ii = i - 1;                              // input col pair base
    int jj = j - 1;                              // input row pair base
    int x_lo = max(ii, 0);
    int x_hi = min(ii + 1, IN_W - 1);
    int y_lo = max(jj, 0);
    int y_hi = min(jj + 1, IN_H - 1);

    long in_b = (long)b * IN_H * IN_W * CV;
    const float4* r0 = in + in_b + (long)(y_lo * IN_W) * CV + cvec;
    const float4* r1 = in + in_b + (long)(y_hi * IN_W) * CV + cvec;

    float4 p00 = __ldg(r0 + (long)x_lo * CV);
    float4 p01 = __ldg(r0 + (long)x_hi * CV);
    float4 p10 = __ldg(r1 + (long)x_lo * CV);
    float4 p11 = __ldg(r1 + (long)x_hi * CV);

    // horizontal lerps: ox_a = 2i-1 -> dx=0.25 ; ox_b = 2i -> dx=0.75
    float4 ta = lerp4(p00, p01, 0.25f);
    float4 tb = lerp4(p00, p01, 0.75f);
    float4 ba = lerp4(p10, p11, 0.25f);
    float4 bb = lerp4(p10, p11, 0.75f);

    int ox_a = 2 * i - 1;
    int ox_b = 2 * i;
    int oy_a = 2 * j - 1;
    int oy_b = 2 * j;

    bool wxa = (i >= 1);
    bool wxb = (i <= 255);
    bool wya = (j >= 1);
    bool wyb = (j <= 255);

    long out_b = (long)b * OUT_H * OUT_W * CV + cvec;

    if (wya) {  // output row oy_a, dy = 0.25
        long row = out_b + (long)(oy_a * OUT_W) * CV;
        if (wxa) out[row + (long)ox_a * CV] = lerp4(ta, ba, 0.25f);
        if (wxb) out[row + (long)ox_b * CV] = lerp4(tb, bb, 0.25f);
    }
    if (wyb) {  // output row oy_b, dy = 0.75
        long row = out_b + (long)(oy_b * OUT_W) * CV;
        if (wxa) out[row + (long)ox_a * CV] = lerp4(ta, ba, 0.75f);
        if (wxb) out[row + (long)ox_b * CV] = lerp4(tb, bb, 0.75f);
    }
}

extern "C" void kernel_launch(void* const* d_in, const int* in_sizes, int n_in,
                              void* d_out, int out_size) {
    const float4* in  = (const float4*)d_in[0];
    float4*       out = (float4*)d_out;

    dim3 block(16, 16);                 // tx = channel chunk, ty = column group
    dim3 grid(17, 257, 8);              // 257 column groups, 257 row groups, 8 batches
    bilerp2x_final_kernel<<<grid, block>>>(in, out);
}